// round 13
// baseline (speedup 1.0000x reference)
#include <cuda_runtime.h>
#include <cuda_bf16.h>
#include <cstdint>

#define B_TOT 32768
#define EMB   256
#define ADIM  64
#define NH    2
#define KN    16
#define K2_WARPS 8
#define K2_R     8   // rows per warp; grid = 32768/(8*8) = 512

// Scratch (device globals; no allocation allowed)
__device__ float g_QK [B_TOT * 512];   // [b][h*256+d]
__device__ float g_CTX[B_TOT * 512];   // [b][h*256+d]
__device__ float g_M  [512 * 256];     // [hd][e]

__device__ __forceinline__ void mma_tf32(float c[4], const uint32_t a[4], const uint32_t b[2]) {
    asm volatile(
        "mma.sync.aligned.m16n8k8.row.col.f32.tf32.tf32.f32 "
        "{%0,%1,%2,%3}, {%4,%5,%6,%7}, {%8,%9}, {%0,%1,%2,%3};"
        : "+f"(c[0]), "+f"(c[1]), "+f"(c[2]), "+f"(c[3])
        : "r"(a[0]), "r"(a[1]), "r"(a[2]), "r"(a[3]), "r"(b[0]), "r"(b[1]));
}

__device__ __forceinline__ void ldsm4(uint32_t& r0, uint32_t& r1, uint32_t& r2, uint32_t& r3,
                                      uint32_t addr) {
    asm volatile("ldmatrix.sync.aligned.m8n8.x4.shared.b16 {%0,%1,%2,%3}, [%4];"
                 : "=r"(r0), "=r"(r1), "=r"(r2), "=r"(r3) : "r"(addr));
}

__device__ __forceinline__ void cp16(uint32_t dst, const void* src) {
    asm volatile("cp.async.cg.shared.global [%0], [%1], 16;" :: "r"(dst), "l"(src));
}
__device__ __forceinline__ void cp_commit() {
    asm volatile("cp.async.commit_group;");
}
template<int N>
__device__ __forceinline__ void cp_wait() {
    asm volatile("cp.async.wait_group %0;" :: "n"(N));
}

// ---------------------------------------------------------------------------
// K0: g_M[hd][e] = sum_a Wq[h*64+a][e] * Wk[h*64+a][d].  512 blocks x 256 thr.
// ---------------------------------------------------------------------------
__global__ __launch_bounds__(256) void k0_M(
    const float* __restrict__ Wq, const float* __restrict__ Wk)
{
    __shared__ float wk_sm[64];
    const int hd = blockIdx.x, h = hd >> 8, d = hd & 255;
    const int t = threadIdx.x;
    if (t < 64) wk_sm[t] = __ldg(&Wk[(h * 64 + t) * 256 + d]);
    __syncthreads();
    float acc = 0.f;
    #pragma unroll 8
    for (int a = 0; a < 64; a++)
        acc += wk_sm[a] * __ldg(&Wq[(h * 64 + a) * 256 + t]);
    g_M[hd * 256 + t] = acc;
}

// ---------------------------------------------------------------------------
// tf32 GEMM, cp.async 3-stage ring (16-k chunks), ldmatrix fragment loads.
// Block tile 128x128, 256 threads (8 warps), warp tile 32(M) x 64(N).
// ---------------------------------------------------------------------------
template<int KTOT, bool IS_K1>
__global__ __launch_bounds__(256) void gemm_tf32(
    const float* __restrict__ Ap,
    const float* __restrict__ Bp_in,
    float* __restrict__ Dp_in,
    int NTOT,
    const float* __restrict__ bout,
    const float* __restrict__ center,
    const int* __restrict__ mask)
{
    __shared__ float As[3][128][16];   // 24 KB
    __shared__ float Bs[3][128][16];   // 24 KB

    const float* Aptr = IS_K1 ? Ap   : g_CTX;
    const float* Bptr = IS_K1 ? g_M  : Bp_in;
    float*       Dptr = IS_K1 ? g_QK : Dp_in;

    const int t    = threadIdx.x;
    const int w    = t >> 5, lane = t & 31;
    const int g    = lane >> 2, tid4 = lane & 3;
    const int wm   = w & 3;
    const int wn   = w >> 2;
    const int m_blk = blockIdx.x * 128;
    const int n_blk = blockIdx.y * 128;

    const uint32_t a_base = (uint32_t)__cvta_generic_to_shared(&As[0][0][0]);
    const uint32_t b_base = (uint32_t)__cvta_generic_to_shared(&Bs[0][0][0]);

    constexpr int NCH = KTOT / 16;

    const int row_st = t >> 2;
    const int kq_st  = t & 3;

    auto stage = [&](int ch, int buf) {
        #pragma unroll
        for (int i = 0; i < 2; i++) {
            const int row = row_st + i * 64;
            const int c4p = kq_st ^ ((row >> 1) & 3);
            const uint32_t off = (uint32_t)(buf * 8192 + row * 64 + c4p * 16);
            cp16(a_base + off, Aptr + (size_t)(m_blk + row) * KTOT + ch * 16 + kq_st * 4);
            cp16(b_base + off, Bptr + (size_t)(n_blk + row) * KTOT + ch * 16 + kq_st * 4);
        }
    };

    const int arow0     = wm * 32 + ((lane & 7) | (lane & 8));
    const int awsel     = (lane >> 4) & 1;
    const int brow0     = wn * 64 + (lane & 7) + ((lane >> 4) & 1) * 8;
    const int bwsel     = (lane >> 3) & 1;

    float acc[2][8][4];
    #pragma unroll
    for (int mi = 0; mi < 2; mi++)
        #pragma unroll
        for (int ni = 0; ni < 8; ni++)
            #pragma unroll
            for (int i = 0; i < 4; i++) acc[mi][ni][i] = 0.f;

    stage(0, 0); cp_commit();
    stage(1, 1); cp_commit();

    int sl = 0;
    int sn = 2;
    for (int ch = 0; ch < NCH; ch++) {
        cp_wait<1>();
        __syncthreads();
        if (ch + 2 < NCH) stage(ch + 2, sn);
        cp_commit();

        #pragma unroll
        for (int ks = 0; ks < 2; ks++) {
            const int c4a = ks * 2;
            uint32_t af[2][4];
            #pragma unroll
            for (int mi = 0; mi < 2; mi++) {
                const int row = arow0 + mi * 16;
                const int sw  = (row >> 1) & 3;
                const uint32_t addr = a_base + (uint32_t)(sl * 8192 + row * 64
                                      + (((c4a + awsel) ^ sw) << 4));
                ldsm4(af[mi][0], af[mi][1], af[mi][2], af[mi][3], addr);
            }
            uint32_t bf[8][2];
            #pragma unroll
            for (int p = 0; p < 4; p++) {
                const int row = brow0 + p * 16;
                const int sw  = (row >> 1) & 3;
                const uint32_t addr = b_base + (uint32_t)(sl * 8192 + row * 64
                                      + (((c4a + bwsel) ^ sw) << 4));
                ldsm4(bf[2 * p][0], bf[2 * p][1], bf[2 * p + 1][0], bf[2 * p + 1][1], addr);
            }
            #pragma unroll
            for (int ni = 0; ni < 8; ni++) {
                mma_tf32(acc[0][ni], af[0], bf[ni]);
                mma_tf32(acc[1][ni], af[1], bf[ni]);
            }
        }
        sl = (sl == 2) ? 0 : sl + 1;
        sn = (sn == 2) ? 0 : sn + 1;
    }

    #pragma unroll
    for (int mi = 0; mi < 2; mi++) {
        #pragma unroll
        for (int half = 0; half < 2; half++) {
            const int row = m_blk + wm * 32 + mi * 16 + g + half * 8;
            bool valid = true;
            if (!IS_K1) valid = (__ldg(&mask[row]) != 0);
            #pragma unroll
            for (int ni = 0; ni < 8; ni++) {
                const int col = n_blk + wn * 64 + ni * 8 + tid4 * 2;
                float v0 = acc[mi][ni][half * 2 + 0];
                float v1 = acc[mi][ni][half * 2 + 1];
                if (!IS_K1) {
                    v0 += __ldg(&bout[col]);
                    v1 += __ldg(&bout[col + 1]);
                    if (!valid) {
                        v0 = __ldg(&center[(size_t)row * EMB + col]);
                        v1 = __ldg(&center[(size_t)row * EMB + col + 1]);
                    }
                }
                *(float2*)(Dptr + (size_t)row * NTOT + col) = make_float2(v0, v1);
            }
        }
    }
}

// ---------------------------------------------------------------------------
// K2 v3: warp-autonomous.  8 warps/block; each warp owns one row at a time in
// its private smem slice (neigh 16x260 + qk 512, XOR-16B swizzled), staged by
// cp.async.  No __syncthreads anywhere; softmax fully warp-parallel via shfl.
// Dynamic smem: 8*(16*260 + 512)*4 = 149.5 KB.
// ---------------------------------------------------------------------------
#define K2_NSLICE (KN * 260)            // floats per warp neigh slice
#define K2_SMEM   ((K2_WARPS * (K2_NSLICE + 512)) * 4)

__global__ __launch_bounds__(256) void k2_attn(
    const float* __restrict__ neigh,   // [B][16][256]
    const float* __restrict__ nw)      // [B][16]
{
    extern __shared__ float sm[];
    const int w    = threadIdx.x >> 5;
    const int lane = threadIdx.x & 31;
    const int h    = lane >> 4, j = lane & 15;

    float* n_sm  = sm + w * K2_NSLICE;                       // [16][260]
    float* qk_sm = sm + K2_WARPS * K2_NSLICE + w * 512;      // [512]
    const uint32_t n_base  = (uint32_t)__cvta_generic_to_shared(n_sm);
    const uint32_t qk_base = (uint32_t)__cvta_generic_to_shared(qk_sm);

    for (int r = 0; r < K2_R; r++) {
        const int b = blockIdx.x * (K2_WARPS * K2_R) + w * K2_R + r;

        // ---- stage row b: neigh 1024 f4 (32/lane) + qk 128 f4 (4/lane) ----
        const float4* nsrc = (const float4*)(neigh + (size_t)b * KN * EMB);
        #pragma unroll
        for (int u = 0; u < 32; u++) {
            const int f4 = u * 32 + lane;
            const int jj = f4 >> 6, c4 = f4 & 63;
            const int phys = c4 ^ ((c4 >> 3) & 7);
            cp16(n_base + (uint32_t)((jj * 260 + phys * 4) * 4), nsrc + f4);
        }
        const float4* qsrc = (const float4*)(g_QK + (size_t)b * 512);
        #pragma unroll
        for (int u = 0; u < 4; u++) {
            const int f4 = u * 32 + lane;
            const int hh = f4 >> 6, c4 = f4 & 63;
            const int phys = c4 ^ ((c4 >> 3) & 7);
            cp16(qk_base + (uint32_t)((hh * 256 + phys * 4) * 4), qsrc + f4);
        }
        cp_commit();
        cp_wait<0>();
        __syncwarp();

        // ---- dot: lane (h,j) computes score over 256 dims ----
        float s = 0.f;
        #pragma unroll 8
        for (int c4 = 0; c4 < 64; c4++) {
            const int phys = c4 ^ ((c4 >> 3) & 7);
            const float4 n = *(const float4*)&n_sm[j * 260 + phys * 4];
            const float4 q = *(const float4*)&qk_sm[h * 256 + phys * 4];
            s += n.x * q.x + n.y * q.y + n.z * q.z + n.w * q.w;
        }
        s *= 0.125f;   // 1/sqrt(64)

        // ---- softmax * weights, renorm — warp-parallel in 16-lane groups ----
        float m = s;
        #pragma unroll
        for (int mm = 1; mm < 16; mm <<= 1)
            m = fmaxf(m, __shfl_xor_sync(0xffffffff, m, mm));
        float e = expf(s - m);
        float Se = e;
        #pragma unroll
        for (int mm = 1; mm < 16; mm <<= 1)
            Se += __shfl_xor_sync(0xffffffff, Se, mm);
        float a = (e / Se) * __ldg(&nw[(size_t)b * KN + j]);
        float den = a;
        #pragma unroll
        for (int mm = 1; mm < 16; mm <<= 1)
            den += __shfl_xor_sync(0xffffffff, den, mm);
        a = a / (den + 1e-8f);

        // ---- ctx: lane handles 4 f4 output chunks ----
        #pragma unroll
        for (int c = 0; c < 4; c++) {
            const int hh = c >> 1;
            const int c4 = (c & 1) * 32 + lane;
            const int phys = c4 ^ ((c4 >> 3) & 7);
            float4 acc = make_float4(0.f, 0.f, 0.f, 0.f);
            #pragma unroll
            for (int jj = 0; jj < 16; jj++) {
                const float av = __shfl_sync(0xffffffff, a, (hh << 4) | jj);
                const float4 n = *(const float4*)&n_sm[jj * 260 + phys * 4];
                acc.x += av * n.x;
                acc.y += av * n.y;
                acc.z += av * n.z;
                acc.w += av * n.w;
            }
            *(float4*)(g_CTX + (size_t)b * 512 + c * 128 + lane * 4) = acc;
        }
        __syncwarp();   // all lanes done reading n_sm before next stage
    }
}

// ---------------------------------------------------------------------------
extern "C" void kernel_launch(void* const* d_in, const int* in_sizes, int n_in,
                              void* d_out, int out_size)
{
    const float* center = (const float*)d_in[0];
    const float* neigh  = (const float*)d_in[1];
    const float* nw     = (const float*)d_in[2];
    const int*   vmask  = (const int*)d_in[3];
    const float* Wq     = (const float*)d_in[4];
    const float* Wk     = (const float*)d_in[5];
    const float* Wout   = (const float*)d_in[6];
    const float* bout   = (const float*)d_in[7];
    float*       out    = (float*)d_out;

    cudaFuncSetAttribute(k2_attn, cudaFuncAttributeMaxDynamicSharedMemorySize, K2_SMEM);

    k0_M<<<512, 256>>>(Wq, Wk);
    // QK[32768,512] = center[32768,256] @ M^T
    gemm_tf32<256, true><<<dim3(256, 4), 256>>>(center, nullptr, nullptr, 512,
                                                nullptr, nullptr, nullptr);
    k2_attn<<<B_TOT / (K2_WARPS * K2_R), 256, K2_SMEM>>>(neigh, nw);
    // OUT[32768,256] = CTX[32768,512] @ Wout^T + bias, masked
    gemm_tf32<512, false><<<dim3(256, 2), 256>>>(nullptr, Wout, out, 256,
                                                 bout, center, vmask);
}